// round 3
// baseline (speedup 1.0000x reference)
#include <cuda_runtime.h>
#include <cuda_fp16.h>

// RadiosityPropagater — N=4096, 64 tail lights, 3 bounces.
//  bounce1: sparse gather over 64 light columns (B0 zero elsewhere), fused combine -> g_B.
//  build:   full O(N^2) pass; gathers with B1 AND materializes F_T[j][i] (fp16, x1024).
//  combine: unrolled 32-split reduce (thread per element) -> g_B (= B2).
//  matvec:  block owns 32 i x ALL j over stored F_T; smem slice-reduce; final
//           emis/brdf/relu applied inline -> d_out. No global partials for bounce 3.
// Deterministic: no float atomics anywhere.

#define NMAX    4096
#define NLIGHTS 64
#define BLK     256
#define JT2     128
#define JS2     (NMAX / JT2)       // 32 j-splits in build
#define FSCALE  1024.0f
#define INV_S   (1.0f / 1024.0f)

__device__ float  g_part[JS2 * NMAX * 3];       // build-pass partial gathers
__device__ float  g_B[NMAX * 3];                // radiosity between bounces
__device__ __half g_F[(size_t)NMAX * NMAX];     // F_T[j][i] = 1024 * F[i][j]

__device__ __forceinline__ float frcp(float x) {
    float r;
    asm("rcp.approx.ftz.f32 %0, %1;" : "=f"(r) : "f"(x));
    return r;
}

__device__ __forceinline__ float snf_scale(const float* s, const float* g,
                                           const float* nf, int j) {
    return s[3*j] * s[3*j+1] * g[j] * nf[j] * FSCALE;
}

// ---------------------------------------------------------------- bounce 1
__global__ void __launch_bounds__(BLK) bounce1_kernel(
        const float* __restrict__ means,  const float* __restrict__ geo,
        const float* __restrict__ scales, const float* __restrict__ normals,
        const float* __restrict__ nf,     const float* __restrict__ emis,
        const float* __restrict__ brdf,   int N) {
    __shared__ float4 sM[NLIGHTS];   // m.xyz, b0'
    __shared__ float4 sS[NLIGHTS];   // scaled n.xyz, b1'
    __shared__ float  sC[NLIGHTS];   // b2'
    int tid = threadIdx.x;
    if (tid < NLIGHTS) {
        int jg = N - NLIGHTS + tid;
        float a = snf_scale(scales, geo, nf, jg);
        sM[tid] = make_float4(means[3*jg], means[3*jg+1], means[3*jg+2],
                              emis[3*jg] * INV_S);
        sS[tid] = make_float4(normals[3*jg] * a, normals[3*jg+1] * a,
                              normals[3*jg+2] * a, emis[3*jg+1] * INV_S);
        sC[tid] = emis[3*jg+2] * INV_S;
    }
    __syncthreads();

    int i = blockIdx.x * BLK + tid;
    float rx = means[3*i],   ry = means[3*i+1],   rz = means[3*i+2];
    float nx = normals[3*i], ny = normals[3*i+1], nz = normals[3*i+2];
    float a0 = 0.f, a1 = 0.f, a2 = 0.f;
    #pragma unroll 8
    for (int j = 0; j < NLIGHTS; j++) {
        float4 M = sM[j]; float4 S = sS[j]; float c = sC[j];
        float dx = M.x - rx, dy = M.y - ry, dz = M.z - rz;
        float d2 = fmaf(dx, dx, fmaf(dy, dy, fmaf(dz, dz, 1e-8f)));
        float r  = frcp(d2);
        float rf = r * fminf(fmaxf(r, 1e-4f), 1.0f);
        float pi_ = fmaxf(fmaf(dx, nx,  fmaf(dy, ny,  dz * nz)),  0.f);
        float pj_ = fmaxf(-fmaf(dx, S.x, fmaf(dy, S.y, dz * S.z)), 0.f);
        float w = pi_ * (pj_ * rf);
        a0 = fmaf(w, M.w, a0); a1 = fmaf(w, S.w, a1); a2 = fmaf(w, c, a2);
    }
    bool light = (i >= N - NLIGHTS);
    float e0 = emis[3*i], e1 = emis[3*i+1], e2 = emis[3*i+2];
    g_B[3*i]   = light ? e0 : fmaf(brdf[3*i],   a0, e0);
    g_B[3*i+1] = light ? e1 : fmaf(brdf[3*i+1], a1, e1);
    g_B[3*i+2] = light ? e2 : fmaf(brdf[3*i+2], a2, e2);
}

// ------------------------------------------------------- bounce 2 + build F
// Each thread handles two ADJACENT receivers so the F_T store is one
// coalesced half2 per j. Partial gathers per j-split go to private slots.
__global__ void __launch_bounds__(BLK) build_kernel(
        const float* __restrict__ means,  const float* __restrict__ geo,
        const float* __restrict__ scales, const float* __restrict__ normals,
        const float* __restrict__ nf,     int N) {
    __shared__ float4 sM[JT2];
    __shared__ float4 sS[JT2];
    __shared__ float  sC[JT2];
    int tid = threadIdx.x;
    int j0  = blockIdx.y * JT2;
    for (int j = tid; j < JT2; j += BLK) {
        int jg = j0 + j;
        float a = snf_scale(scales, geo, nf, jg);
        sM[j] = make_float4(means[3*jg], means[3*jg+1], means[3*jg+2],
                            g_B[3*jg] * INV_S);
        sS[j] = make_float4(normals[3*jg] * a, normals[3*jg+1] * a,
                            normals[3*jg+2] * a, g_B[3*jg+1] * INV_S);
        sC[j] = g_B[3*jg+2] * INV_S;
    }
    __syncthreads();

    int i0 = blockIdx.x * (BLK * 2) + 2 * tid;
    float rx0 = means[3*i0],     ry0 = means[3*i0+1],   rz0 = means[3*i0+2];
    float nx0 = normals[3*i0],   ny0 = normals[3*i0+1], nz0 = normals[3*i0+2];
    float rx1 = means[3*i0+3],   ry1 = means[3*i0+4],   rz1 = means[3*i0+5];
    float nx1 = normals[3*i0+3], ny1 = normals[3*i0+4], nz1 = normals[3*i0+5];

    float a00=0.f,a01=0.f,a02=0.f, a10=0.f,a11=0.f,a12=0.f;
    __half* fp = g_F + (size_t)j0 * N + i0;

    #pragma unroll 4
    for (int j = 0; j < JT2; j++) {
        float4 M = sM[j]; float4 S = sS[j]; float c = sC[j];
        float dx = M.x - rx0, dy = M.y - ry0, dz = M.z - rz0;
        float d2 = fmaf(dx, dx, fmaf(dy, dy, fmaf(dz, dz, 1e-8f)));
        float r  = frcp(d2);
        float rf = r * fminf(fmaxf(r, 1e-4f), 1.0f);
        float pi_ = fmaxf(fmaf(dx, nx0, fmaf(dy, ny0, dz * nz0)), 0.f);
        float pj_ = fmaxf(-fmaf(dx, S.x, fmaf(dy, S.y, dz * S.z)), 0.f);
        float w0 = pi_ * (pj_ * rf);

        dx = M.x - rx1; dy = M.y - ry1; dz = M.z - rz1;
        d2 = fmaf(dx, dx, fmaf(dy, dy, fmaf(dz, dz, 1e-8f)));
        r  = frcp(d2);
        rf = r * fminf(fmaxf(r, 1e-4f), 1.0f);
        pi_ = fmaxf(fmaf(dx, nx1, fmaf(dy, ny1, dz * nz1)), 0.f);
        pj_ = fmaxf(-fmaf(dx, S.x, fmaf(dy, S.y, dz * S.z)), 0.f);
        float w1 = pi_ * (pj_ * rf);

        a00 = fmaf(w0, M.w, a00); a01 = fmaf(w0, S.w, a01); a02 = fmaf(w0, c, a02);
        a10 = fmaf(w1, M.w, a10); a11 = fmaf(w1, S.w, a11); a12 = fmaf(w1, c, a12);

        *(__half2*)(fp) = __floats2half2_rn(w0, w1);
        fp += N;
    }

    float* p = g_part + (size_t)blockIdx.y * N * 3;
    p[3*i0]   = a00; p[3*i0+1] = a01; p[3*i0+2] = a02;
    p[3*i0+3] = a10; p[3*i0+4] = a11; p[3*i0+5] = a12;
}

// --------------------------------------------- bounce-2 combine (fast path)
// One thread per output ELEMENT (idx = 3*i + c): fully unrolled 32 strided,
// coalesced loads (MLP=32), emis/brdf indexed directly by idx.
__global__ void __launch_bounds__(BLK) combine32_kernel(
        const float* __restrict__ emis, const float* __restrict__ brdf, int N) {
    int idx = blockIdx.x * BLK + threadIdx.x;   // 0 .. 3N-1
    float g = 0.f;
    #pragma unroll
    for (int s = 0; s < JS2; s++)
        g += g_part[(size_t)s * NMAX * 3 + idx];
    bool light = (idx >= 3 * (N - NLIGHTS));
    float e = emis[idx];
    g_B[idx] = light ? e : fmaf(brdf[idx], g, e);
}

// --------------------------------------------------- bounce 3: fused matvec
// Block owns 32 receivers x ALL 4096 j. 8 warps = 8 j-slices of 512.
// B2' staged in dynamic smem as float4 (64KB); slice partials reduced in a
// small smem scratch; emis/brdf/relu applied inline -> d_out.
#define MV_I   32
#define MV_JS  8
#define MV_JT  (NMAX / MV_JS)      // 512

extern __shared__ float4 smv[];    // [NMAX] b' + reduce scratch after it

__global__ void __launch_bounds__(BLK) matvec_kernel(
        const float* __restrict__ emis, const float* __restrict__ brdf,
        int N, float* __restrict__ out) {
    float* sred = (float*)(smv + NMAX);         // MV_I*3*MV_JS = 768 floats
    int tid = threadIdx.x;
    for (int j = tid; j < N; j += BLK)
        smv[j] = make_float4(g_B[3*j] * INV_S, g_B[3*j+1] * INV_S,
                             g_B[3*j+2] * INV_S, 0.f);
    __syncthreads();

    int il = tid & (MV_I - 1);
    int js = tid >> 5;
    int iBase = blockIdx.x * MV_I;
    const __half* fp = g_F + (size_t)(js * MV_JT) * N + iBase + il;

    float c0 = 0.f, c1 = 0.f, c2 = 0.f;
    int jb = js * MV_JT;
    #pragma unroll 8
    for (int j = 0; j < MV_JT; j++) {
        float4 b = smv[jb + j];
        float w = __half2float(*fp);
        fp += N;
        c0 = fmaf(w, b.x, c0); c1 = fmaf(w, b.y, c1); c2 = fmaf(w, b.z, c2);
    }

    sred[(il*3 + 0) * MV_JS + js] = c0;
    sred[(il*3 + 1) * MV_JS + js] = c1;
    sred[(il*3 + 2) * MV_JS + js] = c2;
    __syncthreads();

    if (tid < MV_I * 3) {
        float g = 0.f;
        #pragma unroll
        for (int s = 0; s < MV_JS; s++) g += sred[tid * MV_JS + s];
        int idx = iBase * 3 + tid;
        bool light = (idx >= 3 * (N - NLIGHTS));
        float e = emis[idx];
        float b = light ? e : fmaf(brdf[idx], g, e);
        out[idx] = fmaxf(b, 0.f);
    }
}

extern "C" void kernel_launch(void* const* d_in, const int* in_sizes, int n_in,
                              void* d_out, int out_size) {
    const float* means   = (const float*)d_in[0];
    const float* geo     = (const float*)d_in[1];
    const float* scales  = (const float*)d_in[2];
    // d_in[3] = rots — unused (API parity only, per reference)
    const float* normals = (const float*)d_in[4];
    const float* nf      = (const float*)d_in[5];
    const float* emis    = (const float*)d_in[6];
    const float* brdf    = (const float*)d_in[7];
    float* out = (float*)d_out;

    int N = in_sizes[1];              // 4096
    int nIB = (N + BLK - 1) / BLK;    // 16

    static int attr_done = 0;
    const int mv_smem = NMAX * 16 + MV_I * 3 * MV_JS * 4;   // 65536 + 3072
    if (!attr_done) {
        cudaFuncSetAttribute(matvec_kernel,
                             cudaFuncAttributeMaxDynamicSharedMemorySize, mv_smem);
        attr_done = 1;
    }

    // Bounce 1 (sparse over tail lights, combine fused) -> g_B
    bounce1_kernel<<<nIB, BLK>>>(means, geo, scales, normals, nf, emis, brdf, N);

    // Bounce 2: build F_T + gather partials, then fast unrolled combine -> g_B
    build_kernel<<<dim3(N / (BLK * 2), JS2), BLK>>>(means, geo, scales, normals, nf, N);
    combine32_kernel<<<(N * 3) / BLK, BLK>>>(emis, brdf, N);

    // Bounce 3: fused matvec over F_T (block owns all j) -> d_out
    matvec_kernel<<<N / MV_I, BLK, mv_smem>>>(emis, brdf, N, out);
}

// round 4
// speedup vs baseline: 1.4602x; 1.4602x over previous
#include <cuda_runtime.h>
#include <cuda_fp16.h>

// RadiosityPropagater — N=4096, 64 tail lights, 3 bounces.
//  bounce1: sparse gather over 64 light columns (B0 zero elsewhere), fused combine -> g_B.
//  build:   full O(N^2) pass with packed f32x2 math (2 receivers/thread);
//           gathers with B1 AND materializes F_T[j][i] (fp16, x1024).
//  combine32: unrolled reduce of build partials -> g_B (= B2).
//  matvec:  round-2-style wide-load matvec over stored F_T, partials -> g_part.
//  combine64: unrolled reduce + emis/brdf/relu -> d_out.
// Deterministic: no float atomics anywhere.

#define NMAX    4096
#define NLIGHTS 64
#define BLK     256
#define JT2     128
#define JS2     (NMAX / JT2)       // 32 j-splits in build
#define JT3     64
#define JS3     (NMAX / JT3)       // 64 j-splits in matvec
#define IT3     4
#define FSCALE  1024.0f
#define INV_S   (1.0f / 1024.0f)

typedef unsigned long long ull;

__device__ float  g_part[JS3 * NMAX * 3];       // partial gathers (both passes)
__device__ float  g_B[NMAX * 3];                // radiosity between bounces
__device__ __half g_F[(size_t)NMAX * NMAX];     // F_T[j][i] = 1024 * F[i][j]

__device__ __forceinline__ float frcp(float x) {
    float r; asm("rcp.approx.ftz.f32 %0, %1;" : "=f"(r) : "f"(x)); return r;
}
__device__ __forceinline__ ull pk(float lo, float hi) {
    ull r; asm("mov.b64 %0, {%1, %2};" : "=l"(r) : "f"(lo), "f"(hi)); return r;
}
__device__ __forceinline__ ull sp(float x) {
    ull r; asm("mov.b64 %0, {%1, %1};" : "=l"(r) : "f"(x)); return r;
}
__device__ __forceinline__ void upk(ull v, float& lo, float& hi) {
    asm("mov.b64 {%0, %1}, %2;" : "=f"(lo), "=f"(hi) : "l"(v));
}
__device__ __forceinline__ ull f2fma(ull a, ull b, ull c) {
    ull d; asm("fma.rn.f32x2 %0, %1, %2, %3;" : "=l"(d) : "l"(a), "l"(b), "l"(c)); return d;
}
__device__ __forceinline__ ull f2mul(ull a, ull b) {
    ull d; asm("mul.rn.f32x2 %0, %1, %2;" : "=l"(d) : "l"(a), "l"(b)); return d;
}
__device__ __forceinline__ ull f2add(ull a, ull b) {
    ull d; asm("add.rn.f32x2 %0, %1, %2;" : "=l"(d) : "l"(a), "l"(b)); return d;
}

__device__ __forceinline__ float snf_scale(const float* s, const float* g,
                                           const float* nf, int j) {
    return s[3*j] * s[3*j+1] * g[j] * nf[j] * FSCALE;
}

// ---------------------------------------------------------------- bounce 1
__global__ void __launch_bounds__(BLK) bounce1_kernel(
        const float* __restrict__ means,  const float* __restrict__ geo,
        const float* __restrict__ scales, const float* __restrict__ normals,
        const float* __restrict__ nf,     const float* __restrict__ emis,
        const float* __restrict__ brdf,   int N) {
    __shared__ float4 sM[NLIGHTS];
    __shared__ float4 sS[NLIGHTS];
    __shared__ float  sC[NLIGHTS];
    int tid = threadIdx.x;
    if (tid < NLIGHTS) {
        int jg = N - NLIGHTS + tid;
        float a = snf_scale(scales, geo, nf, jg);
        sM[tid] = make_float4(means[3*jg], means[3*jg+1], means[3*jg+2],
                              emis[3*jg] * INV_S);
        sS[tid] = make_float4(normals[3*jg] * a, normals[3*jg+1] * a,
                              normals[3*jg+2] * a, emis[3*jg+1] * INV_S);
        sC[tid] = emis[3*jg+2] * INV_S;
    }
    __syncthreads();

    int i = blockIdx.x * BLK + tid;
    float rx = means[3*i],   ry = means[3*i+1],   rz = means[3*i+2];
    float nx = normals[3*i], ny = normals[3*i+1], nz = normals[3*i+2];
    float a0 = 0.f, a1 = 0.f, a2 = 0.f;
    #pragma unroll 8
    for (int j = 0; j < NLIGHTS; j++) {
        float4 M = sM[j]; float4 S = sS[j]; float c = sC[j];
        float dx = M.x - rx, dy = M.y - ry, dz = M.z - rz;
        float d2 = fmaf(dx, dx, fmaf(dy, dy, fmaf(dz, dz, 1e-8f)));
        float r  = frcp(d2);
        float rf = r * fminf(fmaxf(r, 1e-4f), 1.0f);
        float pi_ = fmaxf(fmaf(dx, nx,  fmaf(dy, ny,  dz * nz)),  0.f);
        float pj_ = fmaxf(-fmaf(dx, S.x, fmaf(dy, S.y, dz * S.z)), 0.f);
        float w = pi_ * (pj_ * rf);
        a0 = fmaf(w, M.w, a0); a1 = fmaf(w, S.w, a1); a2 = fmaf(w, c, a2);
    }
    bool light = (i >= N - NLIGHTS);
    float e0 = emis[3*i], e1 = emis[3*i+1], e2 = emis[3*i+2];
    g_B[3*i]   = light ? e0 : fmaf(brdf[3*i],   a0, e0);
    g_B[3*i+1] = light ? e1 : fmaf(brdf[3*i+1], a1, e1);
    g_B[3*i+2] = light ? e2 : fmaf(brdf[3*i+2], a2, e2);
}

// ------------------------------------------------------- bounce 2 + build F
// Two adjacent receivers per thread, packed into f32x2 lanes (FFMA2 path).
// Emitter tile stored PRE-SPLATTED in smem so the hot loop has no MOV splats.
__global__ void __launch_bounds__(BLK) build_kernel(
        const float* __restrict__ means,  const float* __restrict__ geo,
        const float* __restrict__ scales, const float* __restrict__ normals,
        const float* __restrict__ nf,     int N) {
    __shared__ ulonglong2 sPa[JT2];   // (Mx, My) splatted
    __shared__ ulonglong2 sPb[JT2];   // (Mz, b0') splatted
    __shared__ ulonglong2 sSa[JT2];   // (Sx, Sy) splatted  (scaled normal)
    __shared__ ulonglong2 sSb[JT2];   // (Sz, b1') splatted
    __shared__ ull        sCp[JT2];   // b2' splatted

    int tid = threadIdx.x;
    int j0  = blockIdx.y * JT2;
    for (int j = tid; j < JT2; j += BLK) {
        int jg = j0 + j;
        float a = snf_scale(scales, geo, nf, jg);
        sPa[j] = make_ulonglong2(sp(means[3*jg]), sp(means[3*jg+1]));
        sPb[j] = make_ulonglong2(sp(means[3*jg+2]), sp(g_B[3*jg] * INV_S));
        sSa[j] = make_ulonglong2(sp(normals[3*jg] * a), sp(normals[3*jg+1] * a));
        sSb[j] = make_ulonglong2(sp(normals[3*jg+2] * a), sp(g_B[3*jg+1] * INV_S));
        sCp[j] = sp(g_B[3*jg+2] * INV_S);
    }
    __syncthreads();

    int i0 = blockIdx.x * (BLK * 2) + 2 * tid;
    ull nrx = pk(-means[3*i0],   -means[3*i0+3]);
    ull nry = pk(-means[3*i0+1], -means[3*i0+4]);
    ull nrz = pk(-means[3*i0+2], -means[3*i0+5]);
    ull nxp = pk(normals[3*i0],   normals[3*i0+3]);
    ull nyp = pk(normals[3*i0+1], normals[3*i0+4]);
    ull nzp = pk(normals[3*i0+2], normals[3*i0+5]);
    const ull epsp = sp(1e-8f);

    ull a0p = 0ull, a1p = 0ull, a2p = 0ull;   // 0x0 == (0.f, 0.f)
    __half* fpo = g_F + (size_t)j0 * N + i0;

    #pragma unroll 4
    for (int j = 0; j < JT2; j++) {
        ulonglong2 Pa = sPa[j], Pb = sPb[j];
        ulonglong2 Sa = sSa[j], Sb = sSb[j];
        ull cp = sCp[j];

        ull dxp = f2add(Pa.x, nrx);
        ull dyp = f2add(Pa.y, nry);
        ull dzp = f2add(Pb.x, nrz);
        ull d2p = f2fma(dxp, dxp, f2fma(dyp, dyp, f2fma(dzp, dzp, epsp)));
        ull pip = f2fma(dxp, nxp,  f2fma(dyp, nyp,  f2mul(dzp, nzp)));
        ull pjp = f2fma(dxp, Sa.x, f2fma(dyp, Sa.y, f2mul(dzp, Sb.x)));

        float d20, d21; upk(d2p, d20, d21);
        float r0 = frcp(d20), r1 = frcp(d21);
        float rf0 = r0 * fminf(fmaxf(r0, 1e-4f), 1.0f);
        float rf1 = r1 * fminf(fmaxf(r1, 1e-4f), 1.0f);
        float pi0, pi1; upk(pip, pi0, pi1);
        float pj0, pj1; upk(pjp, pj0, pj1);
        float w0 = fmaxf(pi0, 0.f) * (fmaxf(-pj0, 0.f) * rf0);
        float w1 = fmaxf(pi1, 0.f) * (fmaxf(-pj1, 0.f) * rf1);

        *(__half2*)(fpo) = __floats2half2_rn(w0, w1);   // F_T[j0+j][i0..i0+1]
        fpo += N;

        ull wp = pk(w0, w1);
        a0p = f2fma(wp, Pb.y, a0p);
        a1p = f2fma(wp, Sb.y, a1p);
        a2p = f2fma(wp, cp,  a2p);
    }

    float a00, a10, a01, a11, a02, a12;
    upk(a0p, a00, a10); upk(a1p, a01, a11); upk(a2p, a02, a12);
    float* p = g_part + (size_t)blockIdx.y * NMAX * 3;
    p[3*i0]   = a00; p[3*i0+1] = a01; p[3*i0+2] = a02;
    p[3*i0+3] = a10; p[3*i0+4] = a11; p[3*i0+5] = a12;
}

// --------------------------------------------- bounce-2 combine (fast path)
__global__ void __launch_bounds__(BLK) combine32_kernel(
        const float* __restrict__ emis, const float* __restrict__ brdf, int N) {
    int idx = blockIdx.x * BLK + threadIdx.x;   // 0 .. 3N-1
    float g = 0.f;
    #pragma unroll
    for (int s = 0; s < JS2; s++)
        g += g_part[(size_t)s * NMAX * 3 + idx];
    bool light = (idx >= 3 * (N - NLIGHTS));
    float e = emis[idx];
    g_B[idx] = light ? e : fmaf(brdf[idx], g, e);
}

// ---------------------------------------- bounce 3: matvec (round-2 style)
// Thread owns 4 consecutive i (one uint2 = 4 fp16 per j-row), block tile is
// 1024 i x 64 j, partials to private g_part slot per j-split.
__global__ void __launch_bounds__(BLK) matvec_kernel(int N) {
    __shared__ float4 sB[JT3];
    int tid = threadIdx.x;
    int j0 = blockIdx.y * JT3;
    for (int j = tid; j < JT3; j += BLK) {
        int jg = j0 + j;
        sB[j] = make_float4(g_B[3*jg] * INV_S, g_B[3*jg+1] * INV_S,
                            g_B[3*jg+2] * INV_S, 0.f);
    }
    __syncthreads();

    int i0 = (blockIdx.x * BLK + tid) * IT3;
    float c00=0.f,c01=0.f,c02=0.f, c10=0.f,c11=0.f,c12=0.f;
    float c20=0.f,c21=0.f,c22=0.f, c30=0.f,c31=0.f,c32=0.f;

    const __half* fp = g_F + (size_t)j0 * N + i0;
    #pragma unroll 4
    for (int j = 0; j < JT3; j++) {
        float4 b = sB[j];
        uint2 wv = *(const uint2*)(fp);
        fp += N;
        float2 f0 = __half22float2(*(const __half2*)&wv.x);
        float2 f1 = __half22float2(*(const __half2*)&wv.y);
        c00 = fmaf(f0.x, b.x, c00); c01 = fmaf(f0.x, b.y, c01); c02 = fmaf(f0.x, b.z, c02);
        c10 = fmaf(f0.y, b.x, c10); c11 = fmaf(f0.y, b.y, c11); c12 = fmaf(f0.y, b.z, c12);
        c20 = fmaf(f1.x, b.x, c20); c21 = fmaf(f1.x, b.y, c21); c22 = fmaf(f1.x, b.z, c22);
        c30 = fmaf(f1.y, b.x, c30); c31 = fmaf(f1.y, b.y, c31); c32 = fmaf(f1.y, b.z, c32);
    }

    float* p = g_part + (size_t)blockIdx.y * NMAX * 3 + 3 * i0;
    ((float4*)p)[0] = make_float4(c00, c01, c02, c10);
    ((float4*)p)[1] = make_float4(c11, c12, c20, c21);
    ((float4*)p)[2] = make_float4(c22, c30, c31, c32);
}

// ------------------------------------------------ final combine (64 splits)
__global__ void __launch_bounds__(BLK) combine64_kernel(
        const float* __restrict__ emis, const float* __restrict__ brdf,
        int N, float* __restrict__ out) {
    int idx = blockIdx.x * BLK + threadIdx.x;   // 0 .. 3N-1
    float g = 0.f;
    #pragma unroll
    for (int s = 0; s < JS3; s++)
        g += g_part[(size_t)s * NMAX * 3 + idx];
    bool light = (idx >= 3 * (N - NLIGHTS));
    float e = emis[idx];
    float b = light ? e : fmaf(brdf[idx], g, e);
    out[idx] = fmaxf(b, 0.f);
}

extern "C" void kernel_launch(void* const* d_in, const int* in_sizes, int n_in,
                              void* d_out, int out_size) {
    const float* means   = (const float*)d_in[0];
    const float* geo     = (const float*)d_in[1];
    const float* scales  = (const float*)d_in[2];
    // d_in[3] = rots — unused (API parity only, per reference)
    const float* normals = (const float*)d_in[4];
    const float* nf      = (const float*)d_in[5];
    const float* emis    = (const float*)d_in[6];
    const float* brdf    = (const float*)d_in[7];
    float* out = (float*)d_out;

    int N = in_sizes[1];              // 4096
    int nIB = (N + BLK - 1) / BLK;    // 16

    // Bounce 1 (sparse over tail lights, combine fused) -> g_B
    bounce1_kernel<<<nIB, BLK>>>(means, geo, scales, normals, nf, emis, brdf, N);

    // Bounce 2: packed-f32x2 build of F_T + gather, then unrolled combine -> g_B
    build_kernel<<<dim3(N / (BLK * 2), JS2), BLK>>>(means, geo, scales, normals, nf, N);
    combine32_kernel<<<(N * 3) / BLK, BLK>>>(emis, brdf, N);

    // Bounce 3: matvec over F_T, then unrolled combine + relu -> d_out
    matvec_kernel<<<dim3(N / (BLK * IT3), JS3), BLK>>>(N);
    combine64_kernel<<<(N * 3) / BLK, BLK>>>(emis, brdf, N, out);
}

// round 5
// speedup vs baseline: 1.5097x; 1.0339x over previous
#include <cuda_runtime.h>
#include <cuda_fp16.h>

// RadiosityPropagater — N=4096, 64 tail lights, 3 bounces.
//  bounce1: sparse gather over 64 light columns (B0 zero elsewhere), fused combine -> g_B.
//  build:   full O(N^2) pass, packed f32x2 math (2 receivers/thread);
//           gathers with B1 AND materializes F_T[j][i] (fp16, x1024).
//  combine32: unrolled reduce of build partials -> g_B (= B2).
//  matvec:  high-occupancy matvec over stored F_T: grid (4,128), explicit
//           8-deep load batching for MLP; partials -> g_part.
//  combine128: unrolled reduce + emis/brdf/relu -> d_out.
// Deterministic: no float atomics anywhere.

#define NMAX    4096
#define NLIGHTS 64
#define BLK     256
#define JT2     128
#define JS2     (NMAX / JT2)       // 32 j-splits in build
#define JT3     32
#define JS3     (NMAX / JT3)       // 128 j-splits in matvec
#define IT3     4
#define FSCALE  1024.0f
#define INV_S   (1.0f / 1024.0f)

typedef unsigned long long ull;

__device__ float  g_part[JS3 * NMAX * 3];       // partial gathers (both passes)
__device__ float  g_B[NMAX * 3];                // radiosity between bounces
__device__ __half g_F[(size_t)NMAX * NMAX];     // F_T[j][i] = 1024 * F[i][j]

__device__ __forceinline__ float frcp(float x) {
    float r; asm("rcp.approx.ftz.f32 %0, %1;" : "=f"(r) : "f"(x)); return r;
}
__device__ __forceinline__ ull pk(float lo, float hi) {
    ull r; asm("mov.b64 %0, {%1, %2};" : "=l"(r) : "f"(lo), "f"(hi)); return r;
}
__device__ __forceinline__ ull sp(float x) {
    ull r; asm("mov.b64 %0, {%1, %1};" : "=l"(r) : "f"(x)); return r;
}
__device__ __forceinline__ void upk(ull v, float& lo, float& hi) {
    asm("mov.b64 {%0, %1}, %2;" : "=f"(lo), "=f"(hi) : "l"(v));
}
__device__ __forceinline__ ull f2fma(ull a, ull b, ull c) {
    ull d; asm("fma.rn.f32x2 %0, %1, %2, %3;" : "=l"(d) : "l"(a), "l"(b), "l"(c)); return d;
}
__device__ __forceinline__ ull f2mul(ull a, ull b) {
    ull d; asm("mul.rn.f32x2 %0, %1, %2;" : "=l"(d) : "l"(a), "l"(b)); return d;
}
__device__ __forceinline__ ull f2add(ull a, ull b) {
    ull d; asm("add.rn.f32x2 %0, %1, %2;" : "=l"(d) : "l"(a), "l"(b)); return d;
}

__device__ __forceinline__ float snf_scale(const float* s, const float* g,
                                           const float* nf, int j) {
    return s[3*j] * s[3*j+1] * g[j] * nf[j] * FSCALE;
}

// ---------------------------------------------------------------- bounce 1
__global__ void __launch_bounds__(BLK) bounce1_kernel(
        const float* __restrict__ means,  const float* __restrict__ geo,
        const float* __restrict__ scales, const float* __restrict__ normals,
        const float* __restrict__ nf,     const float* __restrict__ emis,
        const float* __restrict__ brdf,   int N) {
    __shared__ float4 sM[NLIGHTS];
    __shared__ float4 sS[NLIGHTS];
    __shared__ float  sC[NLIGHTS];
    int tid = threadIdx.x;
    if (tid < NLIGHTS) {
        int jg = N - NLIGHTS + tid;
        float a = snf_scale(scales, geo, nf, jg);
        sM[tid] = make_float4(means[3*jg], means[3*jg+1], means[3*jg+2],
                              emis[3*jg] * INV_S);
        sS[tid] = make_float4(normals[3*jg] * a, normals[3*jg+1] * a,
                              normals[3*jg+2] * a, emis[3*jg+1] * INV_S);
        sC[tid] = emis[3*jg+2] * INV_S;
    }
    __syncthreads();

    int i = blockIdx.x * BLK + tid;
    float rx = means[3*i],   ry = means[3*i+1],   rz = means[3*i+2];
    float nx = normals[3*i], ny = normals[3*i+1], nz = normals[3*i+2];
    float a0 = 0.f, a1 = 0.f, a2 = 0.f;
    #pragma unroll 8
    for (int j = 0; j < NLIGHTS; j++) {
        float4 M = sM[j]; float4 S = sS[j]; float c = sC[j];
        float dx = M.x - rx, dy = M.y - ry, dz = M.z - rz;
        float d2 = fmaf(dx, dx, fmaf(dy, dy, fmaf(dz, dz, 1e-8f)));
        float r  = frcp(d2);
        float rf = r * fminf(fmaxf(r, 1e-4f), 1.0f);
        float pi_ = fmaxf(fmaf(dx, nx,  fmaf(dy, ny,  dz * nz)),  0.f);
        float pj_ = fmaxf(-fmaf(dx, S.x, fmaf(dy, S.y, dz * S.z)), 0.f);
        float w = pi_ * (pj_ * rf);
        a0 = fmaf(w, M.w, a0); a1 = fmaf(w, S.w, a1); a2 = fmaf(w, c, a2);
    }
    bool light = (i >= N - NLIGHTS);
    float e0 = emis[3*i], e1 = emis[3*i+1], e2 = emis[3*i+2];
    g_B[3*i]   = light ? e0 : fmaf(brdf[3*i],   a0, e0);
    g_B[3*i+1] = light ? e1 : fmaf(brdf[3*i+1], a1, e1);
    g_B[3*i+2] = light ? e2 : fmaf(brdf[3*i+2], a2, e2);
}

// ------------------------------------------------------- bounce 2 + build F
// Two adjacent receivers per thread, packed into f32x2 lanes (FFMA2 path).
// Emitter tile stored PRE-SPLATTED in smem so the hot loop has no MOV splats.
__global__ void __launch_bounds__(BLK) build_kernel(
        const float* __restrict__ means,  const float* __restrict__ geo,
        const float* __restrict__ scales, const float* __restrict__ normals,
        const float* __restrict__ nf,     int N) {
    __shared__ ulonglong2 sPa[JT2];   // (Mx, My) splatted
    __shared__ ulonglong2 sPb[JT2];   // (Mz, b0') splatted
    __shared__ ulonglong2 sSa[JT2];   // (Sx, Sy) splatted  (scaled normal)
    __shared__ ulonglong2 sSb[JT2];   // (Sz, b1') splatted
    __shared__ ull        sCp[JT2];   // b2' splatted

    int tid = threadIdx.x;
    int j0  = blockIdx.y * JT2;
    for (int j = tid; j < JT2; j += BLK) {
        int jg = j0 + j;
        float a = snf_scale(scales, geo, nf, jg);
        sPa[j] = make_ulonglong2(sp(means[3*jg]), sp(means[3*jg+1]));
        sPb[j] = make_ulonglong2(sp(means[3*jg+2]), sp(g_B[3*jg] * INV_S));
        sSa[j] = make_ulonglong2(sp(normals[3*jg] * a), sp(normals[3*jg+1] * a));
        sSb[j] = make_ulonglong2(sp(normals[3*jg+2] * a), sp(g_B[3*jg+1] * INV_S));
        sCp[j] = sp(g_B[3*jg+2] * INV_S);
    }
    __syncthreads();

    int i0 = blockIdx.x * (BLK * 2) + 2 * tid;
    ull nrx = pk(-means[3*i0],   -means[3*i0+3]);
    ull nry = pk(-means[3*i0+1], -means[3*i0+4]);
    ull nrz = pk(-means[3*i0+2], -means[3*i0+5]);
    ull nxp = pk(normals[3*i0],   normals[3*i0+3]);
    ull nyp = pk(normals[3*i0+1], normals[3*i0+4]);
    ull nzp = pk(normals[3*i0+2], normals[3*i0+5]);
    const ull epsp = sp(1e-8f);

    ull a0p = 0ull, a1p = 0ull, a2p = 0ull;
    __half* fpo = g_F + (size_t)j0 * N + i0;

    #pragma unroll 4
    for (int j = 0; j < JT2; j++) {
        ulonglong2 Pa = sPa[j], Pb = sPb[j];
        ulonglong2 Sa = sSa[j], Sb = sSb[j];
        ull cp = sCp[j];

        ull dxp = f2add(Pa.x, nrx);
        ull dyp = f2add(Pa.y, nry);
        ull dzp = f2add(Pb.x, nrz);
        ull d2p = f2fma(dxp, dxp, f2fma(dyp, dyp, f2fma(dzp, dzp, epsp)));
        ull pip = f2fma(dxp, nxp,  f2fma(dyp, nyp,  f2mul(dzp, nzp)));
        ull pjp = f2fma(dxp, Sa.x, f2fma(dyp, Sa.y, f2mul(dzp, Sb.x)));

        float d20, d21; upk(d2p, d20, d21);
        float r0 = frcp(d20), r1 = frcp(d21);
        float rf0 = r0 * fminf(fmaxf(r0, 1e-4f), 1.0f);
        float rf1 = r1 * fminf(fmaxf(r1, 1e-4f), 1.0f);
        float pi0, pi1; upk(pip, pi0, pi1);
        float pj0, pj1; upk(pjp, pj0, pj1);
        float w0 = fmaxf(pi0, 0.f) * (fmaxf(-pj0, 0.f) * rf0);
        float w1 = fmaxf(pi1, 0.f) * (fmaxf(-pj1, 0.f) * rf1);

        *(__half2*)(fpo) = __floats2half2_rn(w0, w1);   // F_T[j0+j][i0..i0+1]
        fpo += N;

        ull wp = pk(w0, w1);
        a0p = f2fma(wp, Pb.y, a0p);
        a1p = f2fma(wp, Sb.y, a1p);
        a2p = f2fma(wp, cp,  a2p);
    }

    float a00, a10, a01, a11, a02, a12;
    upk(a0p, a00, a10); upk(a1p, a01, a11); upk(a2p, a02, a12);
    float* p = g_part + (size_t)blockIdx.y * NMAX * 3;
    p[3*i0]   = a00; p[3*i0+1] = a01; p[3*i0+2] = a02;
    p[3*i0+3] = a10; p[3*i0+4] = a11; p[3*i0+5] = a12;
}

// --------------------------------------------- bounce-2 combine (fast path)
__global__ void __launch_bounds__(BLK) combine32_kernel(
        const float* __restrict__ emis, const float* __restrict__ brdf, int N) {
    int idx = blockIdx.x * BLK + threadIdx.x;   // 0 .. 3N-1
    float g = 0.f;
    #pragma unroll
    for (int s = 0; s < JS2; s++)
        g += g_part[(size_t)s * NMAX * 3 + idx];
    bool light = (idx >= 3 * (N - NLIGHTS));
    float e = emis[idx];
    g_B[idx] = light ? e : fmaf(brdf[idx], g, e);
}

// --------------------------------------- bounce 3: high-concurrency matvec
// Thread owns 4 consecutive i; block tile = 1024 i x 32 j; grid (4,128) =
// 512 blocks (~28 warps/SM). Loads batched 8-deep explicitly for MLP=8.
__global__ void __launch_bounds__(BLK) matvec_kernel(int N) {
    __shared__ float4 sB[JT3];
    int tid = threadIdx.x;
    int j0 = blockIdx.y * JT3;
    if (tid < JT3) {
        int jg = j0 + tid;
        sB[tid] = make_float4(g_B[3*jg] * INV_S, g_B[3*jg+1] * INV_S,
                              g_B[3*jg+2] * INV_S, 0.f);
    }
    __syncthreads();

    int i0 = (blockIdx.x * BLK + tid) * IT3;
    float c00=0.f,c01=0.f,c02=0.f, c10=0.f,c11=0.f,c12=0.f;
    float c20=0.f,c21=0.f,c22=0.f, c30=0.f,c31=0.f,c32=0.f;

    const __half* fp = g_F + (size_t)j0 * N + i0;
    #pragma unroll
    for (int jo = 0; jo < JT3; jo += 8) {
        uint2 w[8];
        #pragma unroll
        for (int u = 0; u < 8; u++)
            w[u] = *(const uint2*)(fp + (size_t)(jo + u) * N);
        #pragma unroll
        for (int u = 0; u < 8; u++) {
            float4 b = sB[jo + u];
            float2 f0 = __half22float2(*(const __half2*)&w[u].x);
            float2 f1 = __half22float2(*(const __half2*)&w[u].y);
            c00 = fmaf(f0.x, b.x, c00); c01 = fmaf(f0.x, b.y, c01); c02 = fmaf(f0.x, b.z, c02);
            c10 = fmaf(f0.y, b.x, c10); c11 = fmaf(f0.y, b.y, c11); c12 = fmaf(f0.y, b.z, c12);
            c20 = fmaf(f1.x, b.x, c20); c21 = fmaf(f1.x, b.y, c21); c22 = fmaf(f1.x, b.z, c22);
            c30 = fmaf(f1.y, b.x, c30); c31 = fmaf(f1.y, b.y, c31); c32 = fmaf(f1.y, b.z, c32);
        }
    }

    float* p = g_part + (size_t)blockIdx.y * NMAX * 3 + 3 * i0;
    ((float4*)p)[0] = make_float4(c00, c01, c02, c10);
    ((float4*)p)[1] = make_float4(c11, c12, c20, c21);
    ((float4*)p)[2] = make_float4(c22, c30, c31, c32);
}

// ----------------------------------------------- final combine (128 splits)
__global__ void __launch_bounds__(BLK) combine128_kernel(
        const float* __restrict__ emis, const float* __restrict__ brdf,
        int N, float* __restrict__ out) {
    int idx = blockIdx.x * BLK + threadIdx.x;   // 0 .. 3N-1
    float g = 0.f;
    #pragma unroll
    for (int s = 0; s < JS3; s++)
        g += g_part[(size_t)s * NMAX * 3 + idx];
    bool light = (idx >= 3 * (N - NLIGHTS));
    float e = emis[idx];
    float b = light ? e : fmaf(brdf[idx], g, e);
    out[idx] = fmaxf(b, 0.f);
}

extern "C" void kernel_launch(void* const* d_in, const int* in_sizes, int n_in,
                              void* d_out, int out_size) {
    const float* means   = (const float*)d_in[0];
    const float* geo     = (const float*)d_in[1];
    const float* scales  = (const float*)d_in[2];
    // d_in[3] = rots — unused (API parity only, per reference)
    const float* normals = (const float*)d_in[4];
    const float* nf      = (const float*)d_in[5];
    const float* emis    = (const float*)d_in[6];
    const float* brdf    = (const float*)d_in[7];
    float* out = (float*)d_out;

    int N = in_sizes[1];              // 4096
    int nIB = (N + BLK - 1) / BLK;    // 16

    // Bounce 1 (sparse over tail lights, combine fused) -> g_B
    bounce1_kernel<<<nIB, BLK>>>(means, geo, scales, normals, nf, emis, brdf, N);

    // Bounce 2: packed-f32x2 build of F_T + gather, then unrolled combine -> g_B
    build_kernel<<<dim3(N / (BLK * 2), JS2), BLK>>>(means, geo, scales, normals, nf, N);
    combine32_kernel<<<(N * 3) / BLK, BLK>>>(emis, brdf, N);

    // Bounce 3: high-occupancy matvec over F_T, then combine + relu -> d_out
    matvec_kernel<<<dim3(N / (BLK * IT3), JS3), BLK>>>(N);
    combine128_kernel<<<(N * 3) / BLK, BLK>>>(emis, brdf, N, out);
}